// round 8
// baseline (speedup 1.0000x reference)
#include <cuda_runtime.h>
#include <cstdint>

#define NEG 0.1f
#define Bb 4
#define Nn 8192
#define Kk 16
#define CIN 131      // 3 + 128 (logical feat_cat channels)
#define FCLD 132     // row stride: [feat 0..127][xyz 128..130][pad 131]
#define AGGK 1048    // 8 * 131 (real K of the big GEMMs)
#define AGGP 1056    // padded row stride (33 * 32); pad cols statically zero
#define NPTS (Bb*Nn) // 32768

// ---- scratch (static device globals; no runtime allocation) ----
__device__ __align__(16) float g_fc1[NPTS * FCLD];   // 16.5 MB
__device__ __align__(16) float g_fc2[NPTS * FCLD];   // 16.5 MB
__device__ __align__(16) float g_agg[(size_t)NPTS * AGGP]; // 138 MB, cols 1048..1055 stay 0
__device__ __align__(16) float g_f2 [NPTS * 128];    // 16.8 MB
__device__ __align__(16) float g_h1 [NPTS * 128];    // 16.8 MB

__device__ __forceinline__ float lrelu(float v) { return v > 0.f ? v : NEG * v; }

__device__ __forceinline__ uint32_t f2tf32(float f) {
    uint32_t u;
    asm("cvt.rna.tf32.f32 %0, %1;" : "=r"(u) : "f"(f));
    return u;
}

__device__ __forceinline__ void mma_tf32(float4& c,
                                         const uint32_t* a, const uint32_t* b) {
    asm volatile(
        "mma.sync.aligned.m16n8k8.row.col.f32.tf32.tf32.f32 "
        "{%0,%1,%2,%3}, {%4,%5,%6,%7}, {%8,%9}, {%0,%1,%2,%3};"
        : "+f"(c.x), "+f"(c.y), "+f"(c.z), "+f"(c.w)
        : "r"(a[0]), "r"(a[1]), "r"(a[2]), "r"(a[3]), "r"(b[0]), "r"(b[1]));
}

// ============================================================================
// Pack: fc1[p][0..127]=feat, fc1[p][128..130]=xyz, fc1[p][131]=0.
// ============================================================================
__global__ void pack_kernel(const float* __restrict__ xyz,
                            const float* __restrict__ feat,
                            float* __restrict__ fc1, float* __restrict__ fc2) {
    int tid = blockIdx.x * blockDim.x + threadIdx.x;
    const int total = NPTS * FCLD;
    if (tid >= total) return;
    int c = tid % FCLD;
    int p = tid / FCLD;
    int b = p >> 13;
    int n = p & (Nn - 1);
    float v;
    if (c < 128)       v = feat[((size_t)b * 128 + c) * Nn + n];
    else if (c < 131)  v = xyz[((size_t)b * 3 + (c - 128)) * Nn + n];
    else               v = 0.f;
    fc1[tid] = v;
    if (c >= 128) fc2[tid] = v;
}

// ============================================================================
// Stage A (R6 hoisted-weight version — measured 71-74us vs 86us baseline):
// per point gather K=16 neighbors, w = lrelu(wn_w@rel + wn_b),
// agg[o][c] = sum_k w[o,k] * featcat[c,k].  Output row stride AGGP (padded).
// Lane (k&15) computes neighbor k's 8 w values once; agg loop shfl-broadcasts.
// ============================================================================
__global__ void __launch_bounds__(256) stage_a_kernel(
    const float* __restrict__ fc, const int* __restrict__ idx,
    const float* __restrict__ wn_w, const float* __restrict__ wn_b,
    float* __restrict__ agg)
{
    __shared__ float sww[24];
    __shared__ float swb[8];
    const int t = threadIdx.x;
    if (t < 24) sww[t] = wn_w[t];
    if (t < 8)  swb[t] = wn_b[t];
    __syncthreads();

    const int warp = t >> 5, lane = t & 31;
    const int p = blockIdx.x * 8 + warp;
    const int b = p >> 13;

    const float* crow = fc + (size_t)p * FCLD;
    const float cx = crow[128], cy = crow[129], cz = crow[130];
    const int* ip = idx + (size_t)p * Kk;

    // ---- hoisted weight-net: lane l computes w[8] for neighbor k = l & 15 ----
    const int lane16 = lane & 15;
    const int m_mine = ip[lane16];
    const float* rowm = fc + (size_t)(b * Nn + m_mine) * FCLD;
    const float rxm = rowm[128] - cx, rym = rowm[129] - cy, rzm = rowm[130] - cz;
    float wv[8];
    #pragma unroll
    for (int o = 0; o < 8; o++)
        wv[o] = lrelu(sww[o*3]*rxm + sww[o*3+1]*rym + sww[o*3+2]*rzm + swb[o]);

    float acc0[8], acc1[8], acc2[8], acc3[8], acc4[8];
    #pragma unroll
    for (int o = 0; o < 8; o++) { acc0[o]=0.f; acc1[o]=0.f; acc2[o]=0.f; acc3[o]=0.f; acc4[o]=0.f; }

    const int phys0 = (lane < 3) ? (128 + lane) : (lane - 3);

    #pragma unroll 4
    for (int k = 0; k < Kk; k++) {
        const int m = __shfl_sync(0xffffffffu, m_mine, k);
        const float* row = fc + ((size_t)(b * Nn + m)) * FCLD;
        float w[8];
        #pragma unroll
        for (int o = 0; o < 8; o++) w[o] = __shfl_sync(0xffffffffu, wv[o], k);
        float f0 = row[phys0];
        float f1 = row[lane + 29];
        float f2 = row[lane + 61];
        float f3 = row[lane + 93];
        float f4 = (lane < 3) ? row[lane + 125] : 0.f;
        #pragma unroll
        for (int o = 0; o < 8; o++) {
            acc0[o] += w[o] * f0;
            acc1[o] += w[o] * f1;
            acc2[o] += w[o] * f2;
            acc3[o] += w[o] * f3;
            acc4[o] += w[o] * f4;
        }
    }

    float* out = agg + (size_t)p * AGGP;
    #pragma unroll
    for (int o = 0; o < 8; o++) {
        out[o*CIN + lane]       = acc0[o];
        out[o*CIN + lane + 32]  = acc1[o];
        out[o*CIN + lane + 64]  = acc2[o];
        out[o*CIN + lane + 96]  = acc3[o];
        if (lane < 3) out[o*CIN + lane + 128] = acc4[o];
    }
}

// ============================================================================
// tf32 tensor-core GEMM — EXACT R5 structure (fastest measured GEMM).
// out[m][j] = act(sum_k A[m][k]*W[j][k] + bias[j]).
// A: [M x lda] row-major fp32 (lda >= K, padded cols must be zero).
// W: [128 x Kreal] row-major fp32 (loads predicated past Kreal).
// BM=BN=128, BK=32, 256 threads, warp tile 32x64 (2x8 m16n8k8 frags).
// Single-buffered; scalar fragment loads hit banks (4g+tg) mod 32 — all 32
// distinct, conflict-free. (R6 reg-pipelining and R7 LDS.64-permute both
// measured slower; do not reintroduce.)
// ============================================================================
__global__ void __launch_bounds__(256) gemm_tf32_kernel(
    const float* __restrict__ A, const float* __restrict__ W,
    const float* __restrict__ bias, float* __restrict__ out,
    int Kreal, int lda, int ldout, int do_relu)
{
    __shared__ __align__(16) uint32_t As[128][36];
    __shared__ __align__(16) uint32_t Ws[128][36];

    const int t    = threadIdx.x;
    const int m0   = blockIdx.x << 7;
    const int lr   = t >> 1;            // 0..127 load row
    const int lc0  = (t & 1) << 4;      // 0 or 16

    const int wid  = t >> 5, lane = t & 31;
    const int wm   = (wid & 3) << 5;    // warp m offset: 0,32,64,96
    const int wn   = (wid >> 2) << 6;   // warp n offset: 0,64
    const int g    = lane >> 2;         // 0..7
    const int tg   = lane & 3;          // 0..3

    float4 c[2][8];
    #pragma unroll
    for (int im = 0; im < 2; im++)
        #pragma unroll
        for (int jn = 0; jn < 8; jn++) c[im][jn] = make_float4(0.f,0.f,0.f,0.f);

    const int niter = (Kreal + 31) >> 5;
    const float* Abase = A + (size_t)(m0 + lr) * lda + lc0;
    const float* Wbase = W + (size_t)lr * Kreal + lc0;

    for (int kt = 0; kt < niter; kt++) {
        const int kb = kt << 5;
        // ---- load + convert A tile ----
        #pragma unroll
        for (int i = 0; i < 4; i++) {
            float4 v = *(const float4*)(Abase + kb + 4*i);
            As[lr][lc0 + 4*i + 0] = f2tf32(v.x);
            As[lr][lc0 + 4*i + 1] = f2tf32(v.y);
            As[lr][lc0 + 4*i + 2] = f2tf32(v.z);
            As[lr][lc0 + 4*i + 3] = f2tf32(v.w);
        }
        // ---- load + convert W tile (predicated at Kreal) ----
        #pragma unroll
        for (int i = 0; i < 4; i++) {
            int kg = kb + lc0 + 4*i;
            float4 v = (kg < Kreal) ? *(const float4*)(Wbase + kb + 4*i)
                                    : make_float4(0.f,0.f,0.f,0.f);
            Ws[lr][lc0 + 4*i + 0] = f2tf32(v.x);
            Ws[lr][lc0 + 4*i + 1] = f2tf32(v.y);
            Ws[lr][lc0 + 4*i + 2] = f2tf32(v.z);
            Ws[lr][lc0 + 4*i + 3] = f2tf32(v.w);
        }
        __syncthreads();

        #pragma unroll
        for (int kk = 0; kk < 32; kk += 8) {
            uint32_t a[2][4];
            #pragma unroll
            for (int im = 0; im < 2; im++) {
                int row = wm + (im << 4);
                a[im][0] = As[row + g    ][kk + tg    ];
                a[im][1] = As[row + g + 8][kk + tg    ];
                a[im][2] = As[row + g    ][kk + tg + 4];
                a[im][3] = As[row + g + 8][kk + tg + 4];
            }
            uint32_t bfr[8][2];
            #pragma unroll
            for (int jn = 0; jn < 8; jn++) {
                int col = wn + (jn << 3);
                bfr[jn][0] = Ws[col + g][kk + tg    ];
                bfr[jn][1] = Ws[col + g][kk + tg + 4];
            }
            #pragma unroll
            for (int im = 0; im < 2; im++)
                #pragma unroll
                for (int jn = 0; jn < 8; jn++)
                    mma_tf32(c[im][jn], a[im], bfr[jn]);
        }
        __syncthreads();
    }

    // ---- epilogue: bias + lrelu, write float2 pairs ----
    #pragma unroll
    for (int jn = 0; jn < 8; jn++) {
        int col = wn + (jn << 3) + (tg << 1);
        float b0 = bias[col], b1 = bias[col + 1];
        #pragma unroll
        for (int im = 0; im < 2; im++) {
            int row = m0 + wm + (im << 4) + g;
            float v0 = c[im][jn].x + b0;
            float v1 = c[im][jn].y + b1;
            float v2 = c[im][jn].z + b0;
            float v3 = c[im][jn].w + b1;
            if (do_relu) { v0 = lrelu(v0); v1 = lrelu(v1); v2 = lrelu(v2); v3 = lrelu(v3); }
            *(float2*)(out + (size_t)row * ldout + col)       = make_float2(v0, v1);
            *(float2*)(out + (size_t)(row + 8) * ldout + col) = make_float2(v2, v3);
        }
    }
}

// ============================================================================
// Fused tail: ff = lrelu(m2_w @ h1 + m2_b)  (64 ch), flow = cl_w @ ff + cl_b.
// ============================================================================
__global__ void __launch_bounds__(256) mlp2_kernel(
    const float* __restrict__ h1,
    const float* __restrict__ m2w, const float* __restrict__ m2b,
    const float* __restrict__ clw, const float* __restrict__ clb,
    float* __restrict__ ffout, float* __restrict__ flowout)
{
    __shared__ __align__(16) float sm2[128][64];   // transposed: sm2[c][j]
    __shared__ __align__(16) float xs[8][128];
    __shared__ __align__(16) float sb[64];
    __shared__ __align__(16) float scl[3][64];
    __shared__ float sclb[3];
    __shared__ float ffs[32][65];
    __shared__ float flows[32][3];

    const int t = threadIdx.x;
    for (int i = t; i < 64 * 128; i += 256) {
        int j = i >> 7, c = i & 127;
        sm2[c][j] = m2w[i];
    }
    if (t < 64)  sb[t] = m2b[t];
    if (t < 192) scl[t / 64][t % 64] = clw[t];
    if (t < 3)   sclb[t] = clb[t];
    __syncthreads();

    const int w = t >> 5, lane = t & 31;
    const int p0 = blockIdx.x * 32;

    #pragma unroll
    for (int it = 0; it < 4; it++) {
        int pl = (it << 3) + w;
        int p  = p0 + pl;
        const float* xr = h1 + (size_t)p * 128;
        ((float4*)xs[w])[lane] = ((const float4*)xr)[lane];
        __syncwarp();

        float a0 = sb[2*lane], a1 = sb[2*lane + 1];
        #pragma unroll 4
        for (int c = 0; c < 128; c++) {
            float xc = xs[w][c];
            float2 mv = ((const float2*)sm2[c])[lane];
            a0 += mv.x * xc;
            a1 += mv.y * xc;
        }
        a0 = lrelu(a0);
        a1 = lrelu(a1);
        ffs[pl][2*lane]     = a0;
        ffs[pl][2*lane + 1] = a1;

        float pr0 = scl[0][2*lane]*a0 + scl[0][2*lane+1]*a1;
        float pr1 = scl[1][2*lane]*a0 + scl[1][2*lane+1]*a1;
        float pr2 = scl[2][2*lane]*a0 + scl[2][2*lane+1]*a1;
        #pragma unroll
        for (int off = 16; off > 0; off >>= 1) {
            pr0 += __shfl_down_sync(0xffffffffu, pr0, off);
            pr1 += __shfl_down_sync(0xffffffffu, pr1, off);
            pr2 += __shfl_down_sync(0xffffffffu, pr2, off);
        }
        if (lane == 0) {
            flows[pl][0] = pr0 + sclb[0];
            flows[pl][1] = pr1 + sclb[1];
            flows[pl][2] = pr2 + sclb[2];
        }
        __syncwarp();
    }
    __syncthreads();

    const int b  = p0 >> 13;
    const int n0 = p0 & (Nn - 1);
    for (int i = t; i < 64 * 32; i += 256) {
        int j = i >> 5, nl = i & 31;
        ffout[((size_t)b * 64 + j) * Nn + n0 + nl] = ffs[nl][j];
    }
    if (t < 96) {
        int ii = t / 32, nl = t % 32;
        flowout[((size_t)b * 3 + ii) * Nn + n0 + nl] = flows[nl][ii];
    }
}

// ============================================================================
extern "C" void kernel_launch(void* const* d_in, const int* in_sizes, int n_in,
                              void* d_out, int out_size) {
    const float* xyz    = (const float*)d_in[0];
    const float* feat   = (const float*)d_in[1];
    const int*   knn    = (const int*)  d_in[2];
    const float* wn1_w  = (const float*)d_in[3];
    const float* wn1_b  = (const float*)d_in[4];
    const float* lin1_w = (const float*)d_in[5];
    const float* lin1_b = (const float*)d_in[6];
    const float* wn2_w  = (const float*)d_in[7];
    const float* wn2_b  = (const float*)d_in[8];
    const float* lin2_w = (const float*)d_in[9];
    const float* lin2_b = (const float*)d_in[10];
    const float* m1_w   = (const float*)d_in[11];
    const float* m1_b   = (const float*)d_in[12];
    const float* m2_w   = (const float*)d_in[13];
    const float* m2_b   = (const float*)d_in[14];
    const float* cl_w   = (const float*)d_in[15];
    const float* cl_b   = (const float*)d_in[16];

    float* out = (float*)d_out;
    float* ffout   = out;                       // flow_feat [B,64,N]
    float* flowout = out + (size_t)NPTS * 64;   // flow      [B,3,N]

    static float *fc1 = nullptr, *fc2 = nullptr, *agg = nullptr,
                 *f2 = nullptr, *h1 = nullptr;
    if (!fc1) {
        cudaGetSymbolAddress((void**)&fc1, g_fc1);
        cudaGetSymbolAddress((void**)&fc2, g_fc2);
        cudaGetSymbolAddress((void**)&agg, g_agg);
        cudaGetSymbolAddress((void**)&f2,  g_f2);
        cudaGetSymbolAddress((void**)&h1,  g_h1);
    }

    // pack input features + xyz into point-major rows
    {
        int total = NPTS * FCLD;
        pack_kernel<<<(total + 255) / 256, 256>>>(xyz, feat, fc1, fc2);
    }
    // point conv 1 (tf32 GEMM over padded K=1056, real K=1048)
    stage_a_kernel<<<NPTS / 8, 256>>>(fc1, knn, wn1_w, wn1_b, agg);
    gemm_tf32_kernel<<<NPTS / 128, 256>>>(agg, lin1_w, lin1_b, fc2, AGGK, AGGP, FCLD, 1);
    // point conv 2
    stage_a_kernel<<<NPTS / 8, 256>>>(fc2, knn, wn2_w, wn2_b, agg);
    gemm_tf32_kernel<<<NPTS / 128, 256>>>(agg, lin2_w, lin2_b, f2, AGGK, AGGP, 128, 1);
    // MLP layer 1 (K=128)
    gemm_tf32_kernel<<<NPTS / 128, 256>>>(f2, m1_w, m1_b, h1, 128, 128, 128, 1);
    // MLP layer 2 + conv_last fused, channel-major outputs
    mlp2_kernel<<<NPTS / 32, 256>>>(h1, m2_w, m2_b, cl_w, cl_b, ffout, flowout);
}

// round 9
// speedup vs baseline: 1.4976x; 1.4976x over previous
#include <cuda_runtime.h>
#include <cstdint>

#define NEG 0.1f
#define Bb 4
#define Nn 8192
#define Kk 16
#define CIN 131      // 3 + 128 (logical feat_cat channels)
#define FCLD 132     // row stride: [feat 0..127][xyz 128..130][pad 131]
#define AGGK 1048    // 8 * 131 (real K of the big GEMMs)
#define AGGP 1056    // padded row stride (33 * 32); pad cols statically zero
#define NPTS (Bb*Nn) // 32768

// ---- scratch (static device globals; no runtime allocation) ----
__device__ __align__(16) float g_fc1[NPTS * FCLD];   // 16.5 MB
__device__ __align__(16) float g_fc2[NPTS * FCLD];   // 16.5 MB
__device__ __align__(16) float g_agg[(size_t)NPTS * AGGP]; // 138 MB, cols 1048..1055 stay 0
__device__ __align__(16) float g_f2 [NPTS * 128];    // 16.8 MB
__device__ __align__(16) float g_h1 [NPTS * 128];    // 16.8 MB

__device__ __forceinline__ float lrelu(float v) { return v > 0.f ? v : NEG * v; }

__device__ __forceinline__ uint32_t f2tf32(float f) {
    uint32_t u;
    asm("cvt.rna.tf32.f32 %0, %1;" : "=r"(u) : "f"(f));
    return u;
}

__device__ __forceinline__ void mma_tf32(float4& c,
                                         const uint32_t* a, const uint32_t* b) {
    asm volatile(
        "mma.sync.aligned.m16n8k8.row.col.f32.tf32.tf32.f32 "
        "{%0,%1,%2,%3}, {%4,%5,%6,%7}, {%8,%9}, {%0,%1,%2,%3};"
        : "+f"(c.x), "+f"(c.y), "+f"(c.z), "+f"(c.w)
        : "r"(a[0]), "r"(a[1]), "r"(a[2]), "r"(a[3]), "r"(b[0]), "r"(b[1]));
}

// ============================================================================
// Pack: fc1[p][0..127]=feat, fc1[p][128..130]=xyz, fc1[p][131]=0.
// ============================================================================
__global__ void pack_kernel(const float* __restrict__ xyz,
                            const float* __restrict__ feat,
                            float* __restrict__ fc1, float* __restrict__ fc2) {
    int tid = blockIdx.x * blockDim.x + threadIdx.x;
    const int total = NPTS * FCLD;
    if (tid >= total) return;
    int c = tid % FCLD;
    int p = tid / FCLD;
    int b = p >> 13;
    int n = p & (Nn - 1);
    float v;
    if (c < 128)       v = feat[((size_t)b * 128 + c) * Nn + n];
    else if (c < 131)  v = xyz[((size_t)b * 3 + (c - 128)) * Nn + n];
    else               v = 0.f;
    fc1[tid] = v;
    if (c >= 128) fc2[tid] = v;
}

// ============================================================================
// Stage A (hoisted-weight version — measured 71-74us on healthy runs):
// per point gather K=16 neighbors, w = lrelu(wn_w@rel + wn_b),
// agg[o][c] = sum_k w[o,k] * featcat[c,k].  Output row stride AGGP (padded).
// Lane (k&15) computes neighbor k's 8 w values once; agg loop shfl-broadcasts.
// ============================================================================
__global__ void __launch_bounds__(256) stage_a_kernel(
    const float* __restrict__ fc, const int* __restrict__ idx,
    const float* __restrict__ wn_w, const float* __restrict__ wn_b,
    float* __restrict__ agg)
{
    __shared__ float sww[24];
    __shared__ float swb[8];
    const int t = threadIdx.x;
    if (t < 24) sww[t] = wn_w[t];
    if (t < 8)  swb[t] = wn_b[t];
    __syncthreads();

    const int warp = t >> 5, lane = t & 31;
    const int p = blockIdx.x * 8 + warp;
    const int b = p >> 13;

    const float* crow = fc + (size_t)p * FCLD;
    const float cx = crow[128], cy = crow[129], cz = crow[130];
    const int* ip = idx + (size_t)p * Kk;

    // ---- hoisted weight-net: lane l computes w[8] for neighbor k = l & 15 ----
    const int lane16 = lane & 15;
    const int m_mine = ip[lane16];
    const float* rowm = fc + (size_t)(b * Nn + m_mine) * FCLD;
    const float rxm = rowm[128] - cx, rym = rowm[129] - cy, rzm = rowm[130] - cz;
    float wv[8];
    #pragma unroll
    for (int o = 0; o < 8; o++)
        wv[o] = lrelu(sww[o*3]*rxm + sww[o*3+1]*rym + sww[o*3+2]*rzm + swb[o]);

    float acc0[8], acc1[8], acc2[8], acc3[8], acc4[8];
    #pragma unroll
    for (int o = 0; o < 8; o++) { acc0[o]=0.f; acc1[o]=0.f; acc2[o]=0.f; acc3[o]=0.f; acc4[o]=0.f; }

    const int phys0 = (lane < 3) ? (128 + lane) : (lane - 3);

    #pragma unroll 4
    for (int k = 0; k < Kk; k++) {
        const int m = __shfl_sync(0xffffffffu, m_mine, k);
        const float* row = fc + ((size_t)(b * Nn + m)) * FCLD;
        float w[8];
        #pragma unroll
        for (int o = 0; o < 8; o++) w[o] = __shfl_sync(0xffffffffu, wv[o], k);
        float f0 = row[phys0];
        float f1 = row[lane + 29];
        float f2 = row[lane + 61];
        float f3 = row[lane + 93];
        float f4 = (lane < 3) ? row[lane + 125] : 0.f;
        #pragma unroll
        for (int o = 0; o < 8; o++) {
            acc0[o] += w[o] * f0;
            acc1[o] += w[o] * f1;
            acc2[o] += w[o] * f2;
            acc3[o] += w[o] * f3;
            acc4[o] += w[o] * f4;
        }
    }

    float* out = agg + (size_t)p * AGGP;
    #pragma unroll
    for (int o = 0; o < 8; o++) {
        out[o*CIN + lane]       = acc0[o];
        out[o*CIN + lane + 32]  = acc1[o];
        out[o*CIN + lane + 64]  = acc2[o];
        out[o*CIN + lane + 96]  = acc3[o];
        if (lane < 3) out[o*CIN + lane + 128] = acc4[o];
    }
}

// ============================================================================
// tf32 tensor-core GEMM — EXACT R5 structure (fastest measured GEMM).
// out[m][j] = act(sum_k A[m][k]*W[j][k] + bias[j]).
// A: [M x lda] row-major fp32 (lda >= K, padded cols must be zero).
// W: [128 x Kreal] row-major fp32 (loads predicated past Kreal).
// BM=BN=128, BK=32, 256 threads, warp tile 32x64 (2x8 m16n8k8 frags).
// Single-buffered; scalar fragment loads hit banks (4g+tg) mod 32 — all 32
// distinct, conflict-free. (R6 reg-pipelining and R7 LDS.64-permute both
// measured slower; do not reintroduce.)
// ============================================================================
__global__ void __launch_bounds__(256) gemm_tf32_kernel(
    const float* __restrict__ A, const float* __restrict__ W,
    const float* __restrict__ bias, float* __restrict__ out,
    int Kreal, int lda, int ldout, int do_relu)
{
    __shared__ __align__(16) uint32_t As[128][36];
    __shared__ __align__(16) uint32_t Ws[128][36];

    const int t    = threadIdx.x;
    const int m0   = blockIdx.x << 7;
    const int lr   = t >> 1;            // 0..127 load row
    const int lc0  = (t & 1) << 4;      // 0 or 16

    const int wid  = t >> 5, lane = t & 31;
    const int wm   = (wid & 3) << 5;    // warp m offset: 0,32,64,96
    const int wn   = (wid >> 2) << 6;   // warp n offset: 0,64
    const int g    = lane >> 2;         // 0..7
    const int tg   = lane & 3;          // 0..3

    float4 c[2][8];
    #pragma unroll
    for (int im = 0; im < 2; im++)
        #pragma unroll
        for (int jn = 0; jn < 8; jn++) c[im][jn] = make_float4(0.f,0.f,0.f,0.f);

    const int niter = (Kreal + 31) >> 5;
    const float* Abase = A + (size_t)(m0 + lr) * lda + lc0;
    const float* Wbase = W + (size_t)lr * Kreal + lc0;

    for (int kt = 0; kt < niter; kt++) {
        const int kb = kt << 5;
        // ---- load + convert A tile ----
        #pragma unroll
        for (int i = 0; i < 4; i++) {
            float4 v = *(const float4*)(Abase + kb + 4*i);
            As[lr][lc0 + 4*i + 0] = f2tf32(v.x);
            As[lr][lc0 + 4*i + 1] = f2tf32(v.y);
            As[lr][lc0 + 4*i + 2] = f2tf32(v.z);
            As[lr][lc0 + 4*i + 3] = f2tf32(v.w);
        }
        // ---- load + convert W tile (predicated at Kreal) ----
        #pragma unroll
        for (int i = 0; i < 4; i++) {
            int kg = kb + lc0 + 4*i;
            float4 v = (kg < Kreal) ? *(const float4*)(Wbase + kb + 4*i)
                                    : make_float4(0.f,0.f,0.f,0.f);
            Ws[lr][lc0 + 4*i + 0] = f2tf32(v.x);
            Ws[lr][lc0 + 4*i + 1] = f2tf32(v.y);
            Ws[lr][lc0 + 4*i + 2] = f2tf32(v.z);
            Ws[lr][lc0 + 4*i + 3] = f2tf32(v.w);
        }
        __syncthreads();

        #pragma unroll
        for (int kk = 0; kk < 32; kk += 8) {
            uint32_t a[2][4];
            #pragma unroll
            for (int im = 0; im < 2; im++) {
                int row = wm + (im << 4);
                a[im][0] = As[row + g    ][kk + tg    ];
                a[im][1] = As[row + g + 8][kk + tg    ];
                a[im][2] = As[row + g    ][kk + tg + 4];
                a[im][3] = As[row + g + 8][kk + tg + 4];
            }
            uint32_t bfr[8][2];
            #pragma unroll
            for (int jn = 0; jn < 8; jn++) {
                int col = wn + (jn << 3);
                bfr[jn][0] = Ws[col + g][kk + tg    ];
                bfr[jn][1] = Ws[col + g][kk + tg + 4];
            }
            #pragma unroll
            for (int im = 0; im < 2; im++)
                #pragma unroll
                for (int jn = 0; jn < 8; jn++)
                    mma_tf32(c[im][jn], a[im], bfr[jn]);
        }
        __syncthreads();
    }

    // ---- epilogue: bias + lrelu, write float2 pairs ----
    #pragma unroll
    for (int jn = 0; jn < 8; jn++) {
        int col = wn + (jn << 3) + (tg << 1);
        float b0 = bias[col], b1 = bias[col + 1];
        #pragma unroll
        for (int im = 0; im < 2; im++) {
            int row = m0 + wm + (im << 4) + g;
            float v0 = c[im][jn].x + b0;
            float v1 = c[im][jn].y + b1;
            float v2 = c[im][jn].z + b0;
            float v3 = c[im][jn].w + b1;
            if (do_relu) { v0 = lrelu(v0); v1 = lrelu(v1); v2 = lrelu(v2); v3 = lrelu(v3); }
            *(float2*)(out + (size_t)row * ldout + col)       = make_float2(v0, v1);
            *(float2*)(out + (size_t)(row + 8) * ldout + col) = make_float2(v2, v3);
        }
    }
}

// ============================================================================
// Fused tail: ff = lrelu(m2_w @ h1 + m2_b)  (64 ch), flow = cl_w @ ff + cl_b.
// ============================================================================
__global__ void __launch_bounds__(256) mlp2_kernel(
    const float* __restrict__ h1,
    const float* __restrict__ m2w, const float* __restrict__ m2b,
    const float* __restrict__ clw, const float* __restrict__ clb,
    float* __restrict__ ffout, float* __restrict__ flowout)
{
    __shared__ __align__(16) float sm2[128][64];   // transposed: sm2[c][j]
    __shared__ __align__(16) float xs[8][128];
    __shared__ __align__(16) float sb[64];
    __shared__ __align__(16) float scl[3][64];
    __shared__ float sclb[3];
    __shared__ float ffs[32][65];
    __shared__ float flows[32][3];

    const int t = threadIdx.x;
    for (int i = t; i < 64 * 128; i += 256) {
        int j = i >> 7, c = i & 127;
        sm2[c][j] = m2w[i];
    }
    if (t < 64)  sb[t] = m2b[t];
    if (t < 192) scl[t / 64][t % 64] = clw[t];
    if (t < 3)   sclb[t] = clb[t];
    __syncthreads();

    const int w = t >> 5, lane = t & 31;
    const int p0 = blockIdx.x * 32;

    #pragma unroll
    for (int it = 0; it < 4; it++) {
        int pl = (it << 3) + w;
        int p  = p0 + pl;
        const float* xr = h1 + (size_t)p * 128;
        ((float4*)xs[w])[lane] = ((const float4*)xr)[lane];
        __syncwarp();

        float a0 = sb[2*lane], a1 = sb[2*lane + 1];
        #pragma unroll 4
        for (int c = 0; c < 128; c++) {
            float xc = xs[w][c];
            float2 mv = ((const float2*)sm2[c])[lane];
            a0 += mv.x * xc;
            a1 += mv.y * xc;
        }
        a0 = lrelu(a0);
        a1 = lrelu(a1);
        ffs[pl][2*lane]     = a0;
        ffs[pl][2*lane + 1] = a1;

        float pr0 = scl[0][2*lane]*a0 + scl[0][2*lane+1]*a1;
        float pr1 = scl[1][2*lane]*a0 + scl[1][2*lane+1]*a1;
        float pr2 = scl[2][2*lane]*a0 + scl[2][2*lane+1]*a1;
        #pragma unroll
        for (int off = 16; off > 0; off >>= 1) {
            pr0 += __shfl_down_sync(0xffffffffu, pr0, off);
            pr1 += __shfl_down_sync(0xffffffffu, pr1, off);
            pr2 += __shfl_down_sync(0xffffffffu, pr2, off);
        }
        if (lane == 0) {
            flows[pl][0] = pr0 + sclb[0];
            flows[pl][1] = pr1 + sclb[1];
            flows[pl][2] = pr2 + sclb[2];
        }
        __syncwarp();
    }
    __syncthreads();

    const int b  = p0 >> 13;
    const int n0 = p0 & (Nn - 1);
    for (int i = t; i < 64 * 32; i += 256) {
        int j = i >> 5, nl = i & 31;
        ffout[((size_t)b * 64 + j) * Nn + n0 + nl] = ffs[nl][j];
    }
    if (t < 96) {
        int ii = t / 32, nl = t % 32;
        flowout[((size_t)b * 3 + ii) * Nn + n0 + nl] = flows[nl][ii];
    }
}

// ============================================================================
extern "C" void kernel_launch(void* const* d_in, const int* in_sizes, int n_in,
                              void* d_out, int out_size) {
    const float* xyz    = (const float*)d_in[0];
    const float* feat   = (const float*)d_in[1];
    const int*   knn    = (const int*)  d_in[2];
    const float* wn1_w  = (const float*)d_in[3];
    const float* wn1_b  = (const float*)d_in[4];
    const float* lin1_w = (const float*)d_in[5];
    const float* lin1_b = (const float*)d_in[6];
    const float* wn2_w  = (const float*)d_in[7];
    const float* wn2_b  = (const float*)d_in[8];
    const float* lin2_w = (const float*)d_in[9];
    const float* lin2_b = (const float*)d_in[10];
    const float* m1_w   = (const float*)d_in[11];
    const float* m1_b   = (const float*)d_in[12];
    const float* m2_w   = (const float*)d_in[13];
    const float* m2_b   = (const float*)d_in[14];
    const float* cl_w   = (const float*)d_in[15];
    const float* cl_b   = (const float*)d_in[16];

    float* out = (float*)d_out;
    float* ffout   = out;                       // flow_feat [B,64,N]
    float* flowout = out + (size_t)NPTS * 64;   // flow      [B,3,N]

    static float *fc1 = nullptr, *fc2 = nullptr, *agg = nullptr,
                 *f2 = nullptr, *h1 = nullptr;
    if (!fc1) {
        cudaGetSymbolAddress((void**)&fc1, g_fc1);
        cudaGetSymbolAddress((void**)&fc2, g_fc2);
        cudaGetSymbolAddress((void**)&agg, g_agg);
        cudaGetSymbolAddress((void**)&f2,  g_f2);
        cudaGetSymbolAddress((void**)&h1,  g_h1);
    }

    // pack input features + xyz into point-major rows
    {
        int total = NPTS * FCLD;
        pack_kernel<<<(total + 255) / 256, 256>>>(xyz, feat, fc1, fc2);
    }
    // point conv 1 (tf32 GEMM over padded K=1056, real K=1048)
    stage_a_kernel<<<NPTS / 8, 256>>>(fc1, knn, wn1_w, wn1_b, agg);
    gemm_tf32_kernel<<<NPTS / 128, 256>>>(agg, lin1_w, lin1_b, fc2, AGGK, AGGP, FCLD, 1);
    // point conv 2
    stage_a_kernel<<<NPTS / 8, 256>>>(fc2, knn, wn2_w, wn2_b, agg);
    gemm_tf32_kernel<<<NPTS / 128, 256>>>(agg, lin2_w, lin2_b, f2, AGGK, AGGP, 128, 1);
    // MLP layer 1 (K=128)
    gemm_tf32_kernel<<<NPTS / 128, 256>>>(f2, m1_w, m1_b, h1, 128, 128, 128, 1);
    // MLP layer 2 + conv_last fused, channel-major outputs
    mlp2_kernel<<<NPTS / 32, 256>>>(h1, m2_w, m2_b, cl_w, cl_b, ffout, flowout);
}

// round 10
// speedup vs baseline: 1.5473x; 1.0332x over previous
#include <cuda_runtime.h>
#include <cstdint>

#define NEG 0.1f
#define Bb 4
#define Nn 8192
#define Kk 16
#define CIN 131      // 3 + 128 (logical feat_cat channels)
#define FCLD 132     // row stride: [feat 0..127][xyz 128..130][pad 131]
#define AGGK 1048    // 8 * 131 (real K of the big GEMMs)
#define AGGP 1056    // padded row stride (66 * 16); pad cols statically zero
#define NPTS (Bb*Nn) // 32768

// ---- scratch (static device globals; no runtime allocation) ----
__device__ __align__(16) float g_fc1[NPTS * FCLD];   // 16.5 MB
__device__ __align__(16) float g_fc2[NPTS * FCLD];   // 16.5 MB
__device__ __align__(16) float g_agg[(size_t)NPTS * AGGP]; // 138 MB, tf32 bits; pads stay 0
__device__ __align__(16) float g_f2 [NPTS * 128];    // 16.8 MB (tf32 bits)
__device__ __align__(16) float g_h1 [NPTS * 128];    // 16.8 MB
__device__ __align__(16) float g_w1 [128 * AGGP];    // lin1_w tf32, padded
__device__ __align__(16) float g_w2 [128 * AGGP];    // lin2_w tf32, padded
__device__ __align__(16) float g_wm [128 * 128];     // m1_w tf32

__device__ __forceinline__ float lrelu(float v) { return v > 0.f ? v : NEG * v; }

__device__ __forceinline__ uint32_t f2tf32(float f) {
    uint32_t u;
    asm("cvt.rna.tf32.f32 %0, %1;" : "=r"(u) : "f"(f));
    return u;
}

__device__ __forceinline__ void mma_tf32(float4& c,
                                         const uint32_t* a, const uint32_t* b) {
    asm volatile(
        "mma.sync.aligned.m16n8k8.row.col.f32.tf32.tf32.f32 "
        "{%0,%1,%2,%3}, {%4,%5,%6,%7}, {%8,%9}, {%0,%1,%2,%3};"
        : "+f"(c.x), "+f"(c.y), "+f"(c.z), "+f"(c.w)
        : "r"(a[0]), "r"(a[1]), "r"(a[2]), "r"(a[3]), "r"(b[0]), "r"(b[1]));
}

__device__ __forceinline__ void cpa16(void* smem_ptr, const void* g) {
    uint32_t s = (uint32_t)__cvta_generic_to_shared(smem_ptr);
    asm volatile("cp.async.cg.shared.global [%0], [%1], 16;" :: "r"(s), "l"(g));
}
__device__ __forceinline__ void cpa_commit() {
    asm volatile("cp.async.commit_group;");
}

// ============================================================================
// Weight prep: dst[r][c<ksrc ? tf32(src) : 0], row stride kdst.
// ============================================================================
__global__ void wcvt_kernel(const float* __restrict__ src, float* __restrict__ dst,
                            int ksrc, int kdst, int total) {
    int i = blockIdx.x * blockDim.x + threadIdx.x;
    if (i >= total) return;
    int r = i / kdst, c = i - r * kdst;
    float v = (c < ksrc) ? src[r * ksrc + c] : 0.f;
    dst[i] = __uint_as_float(f2tf32(v));
}

// ============================================================================
// Pack: fc1[p][0..127]=feat, fc1[p][128..130]=xyz, fc1[p][131]=0.
// ============================================================================
__global__ void pack_kernel(const float* __restrict__ xyz,
                            const float* __restrict__ feat,
                            float* __restrict__ fc1, float* __restrict__ fc2) {
    int tid = blockIdx.x * blockDim.x + threadIdx.x;
    const int total = NPTS * FCLD;
    if (tid >= total) return;
    int c = tid % FCLD;
    int p = tid / FCLD;
    int b = p >> 13;
    int n = p & (Nn - 1);
    float v;
    if (c < 128)       v = feat[((size_t)b * 128 + c) * Nn + n];
    else if (c < 131)  v = xyz[((size_t)b * 3 + (c - 128)) * Nn + n];
    else               v = 0.f;
    fc1[tid] = v;
    if (c >= 128) fc2[tid] = v;
}

// ============================================================================
// Stage A (hoisted-weight): per point gather K=16 neighbors,
// w = lrelu(wn_w@rel + wn_b), agg[o][c] = sum_k w[o,k]*featcat[c,k].
// Output stored as tf32 bits (same cvt.rna the GEMM fill used to apply).
// ============================================================================
__global__ void __launch_bounds__(256) stage_a_kernel(
    const float* __restrict__ fc, const int* __restrict__ idx,
    const float* __restrict__ wn_w, const float* __restrict__ wn_b,
    float* __restrict__ agg)
{
    __shared__ float sww[24];
    __shared__ float swb[8];
    const int t = threadIdx.x;
    if (t < 24) sww[t] = wn_w[t];
    if (t < 8)  swb[t] = wn_b[t];
    __syncthreads();

    const int warp = t >> 5, lane = t & 31;
    const int p = blockIdx.x * 8 + warp;
    const int b = p >> 13;

    const float* crow = fc + (size_t)p * FCLD;
    const float cx = crow[128], cy = crow[129], cz = crow[130];
    const int* ip = idx + (size_t)p * Kk;

    const int lane16 = lane & 15;
    const int m_mine = ip[lane16];
    const float* rowm = fc + (size_t)(b * Nn + m_mine) * FCLD;
    const float rxm = rowm[128] - cx, rym = rowm[129] - cy, rzm = rowm[130] - cz;
    float wv[8];
    #pragma unroll
    for (int o = 0; o < 8; o++)
        wv[o] = lrelu(sww[o*3]*rxm + sww[o*3+1]*rym + sww[o*3+2]*rzm + swb[o]);

    float acc0[8], acc1[8], acc2[8], acc3[8], acc4[8];
    #pragma unroll
    for (int o = 0; o < 8; o++) { acc0[o]=0.f; acc1[o]=0.f; acc2[o]=0.f; acc3[o]=0.f; acc4[o]=0.f; }

    const int phys0 = (lane < 3) ? (128 + lane) : (lane - 3);

    #pragma unroll 4
    for (int k = 0; k < Kk; k++) {
        const int m = __shfl_sync(0xffffffffu, m_mine, k);
        const float* row = fc + ((size_t)(b * Nn + m)) * FCLD;
        float w[8];
        #pragma unroll
        for (int o = 0; o < 8; o++) w[o] = __shfl_sync(0xffffffffu, wv[o], k);
        float f0 = row[phys0];
        float f1 = row[lane + 29];
        float f2 = row[lane + 61];
        float f3 = row[lane + 93];
        float f4 = (lane < 3) ? row[lane + 125] : 0.f;
        #pragma unroll
        for (int o = 0; o < 8; o++) {
            acc0[o] += w[o] * f0;
            acc1[o] += w[o] * f1;
            acc2[o] += w[o] * f2;
            acc3[o] += w[o] * f3;
            acc4[o] += w[o] * f4;
        }
    }

    float* out = agg + (size_t)p * AGGP;
    #pragma unroll
    for (int o = 0; o < 8; o++) {
        out[o*CIN + lane]       = __uint_as_float(f2tf32(acc0[o]));
        out[o*CIN + lane + 32]  = __uint_as_float(f2tf32(acc1[o]));
        out[o*CIN + lane + 64]  = __uint_as_float(f2tf32(acc2[o]));
        out[o*CIN + lane + 96]  = __uint_as_float(f2tf32(acc3[o]));
        if (lane < 3) out[o*CIN + lane + 128] = __uint_as_float(f2tf32(acc4[o]));
    }
}

// ============================================================================
// tf32 GEMM, cp.async double-buffered. A and W hold tf32 bit patterns with the
// SAME row stride Kpad (pads zero). out[m][j] = act(sum_k A[m][k]*W[j][k]+b[j]).
// BM=BN=128, BK=16, 2 stages (40KB smem), 256 threads, warp tile 32x64.
// Fragment reads: bank (20g+tg) mod 32 -> 32 distinct, conflict-free.
// ============================================================================
__global__ void __launch_bounds__(256) gemm_tf32_async(
    const float* __restrict__ A, const float* __restrict__ W,
    const float* __restrict__ bias, float* __restrict__ out,
    int Kpad, int ldout, int do_relu, int out_tf32)
{
    __shared__ __align__(16) uint32_t As[2][128][20];
    __shared__ __align__(16) uint32_t Ws[2][128][20];

    const int t    = threadIdx.x;
    const int m0   = blockIdx.x << 7;
    const int lr   = t >> 1;            // 0..127 load row
    const int lcw  = (t & 1) << 3;      // word col 0 or 8

    const int wid  = t >> 5, lane = t & 31;
    const int wm   = (wid & 3) << 5;
    const int wn   = (wid >> 2) << 6;
    const int g    = lane >> 2;
    const int tg   = lane & 3;

    float4 c[2][8];
    #pragma unroll
    for (int im = 0; im < 2; im++)
        #pragma unroll
        for (int jn = 0; jn < 8; jn++) c[im][jn] = make_float4(0.f,0.f,0.f,0.f);

    const int niter = Kpad >> 4;
    const float* Ap = A + (size_t)(m0 + lr) * Kpad + lcw;
    const float* Wp = W + (size_t)lr * Kpad + lcw;

    // ---- prologue: issue stages 0 and 1 ----
    {
        cpa16(&As[0][lr][lcw],     Ap);
        cpa16(&As[0][lr][lcw + 4], Ap + 4);
        cpa16(&Ws[0][lr][lcw],     Wp);
        cpa16(&Ws[0][lr][lcw + 4], Wp + 4);
        cpa_commit();
        cpa16(&As[1][lr][lcw],     Ap + 16);
        cpa16(&As[1][lr][lcw + 4], Ap + 20);
        cpa16(&Ws[1][lr][lcw],     Wp + 16);
        cpa16(&Ws[1][lr][lcw + 4], Wp + 20);
        cpa_commit();
    }

    for (int kt = 0; kt < niter; kt++) {
        if (kt + 1 < niter) asm volatile("cp.async.wait_group 1;");
        else                asm volatile("cp.async.wait_group 0;");
        __syncthreads();
        const int s = kt & 1;

        #pragma unroll
        for (int kk = 0; kk < 16; kk += 8) {
            uint32_t a[2][4];
            #pragma unroll
            for (int im = 0; im < 2; im++) {
                int row = wm + (im << 4);
                a[im][0] = As[s][row + g    ][kk + tg    ];
                a[im][1] = As[s][row + g + 8][kk + tg    ];
                a[im][2] = As[s][row + g    ][kk + tg + 4];
                a[im][3] = As[s][row + g + 8][kk + tg + 4];
            }
            uint32_t bfr[8][2];
            #pragma unroll
            for (int jn = 0; jn < 8; jn++) {
                int col = wn + (jn << 3);
                bfr[jn][0] = Ws[s][col + g][kk + tg    ];
                bfr[jn][1] = Ws[s][col + g][kk + tg + 4];
            }
            #pragma unroll
            for (int im = 0; im < 2; im++)
                #pragma unroll
                for (int jn = 0; jn < 8; jn++)
                    mma_tf32(c[im][jn], a[im], bfr[jn]);
        }
        __syncthreads();

        if (kt + 2 < niter) {
            const int kb = (kt + 2) << 4;
            cpa16(&As[s][lr][lcw],     Ap + kb);
            cpa16(&As[s][lr][lcw + 4], Ap + kb + 4);
            cpa16(&Ws[s][lr][lcw],     Wp + kb);
            cpa16(&Ws[s][lr][lcw + 4], Wp + kb + 4);
            cpa_commit();
        }
    }

    // ---- epilogue: bias + lrelu (+ optional tf32 cvt), float2 stores ----
    #pragma unroll
    for (int jn = 0; jn < 8; jn++) {
        int col = wn + (jn << 3) + (tg << 1);
        float b0 = bias[col], b1 = bias[col + 1];
        #pragma unroll
        for (int im = 0; im < 2; im++) {
            int row = m0 + wm + (im << 4) + g;
            float v0 = c[im][jn].x + b0;
            float v1 = c[im][jn].y + b1;
            float v2 = c[im][jn].z + b0;
            float v3 = c[im][jn].w + b1;
            if (do_relu) { v0 = lrelu(v0); v1 = lrelu(v1); v2 = lrelu(v2); v3 = lrelu(v3); }
            if (out_tf32) {
                v0 = __uint_as_float(f2tf32(v0));
                v1 = __uint_as_float(f2tf32(v1));
                v2 = __uint_as_float(f2tf32(v2));
                v3 = __uint_as_float(f2tf32(v3));
            }
            *(float2*)(out + (size_t)row * ldout + col)       = make_float2(v0, v1);
            *(float2*)(out + (size_t)(row + 8) * ldout + col) = make_float2(v2, v3);
        }
    }
}

// ============================================================================
// Fused tail: ff = lrelu(m2_w @ h1 + m2_b)  (64 ch), flow = cl_w @ ff + cl_b.
// ============================================================================
__global__ void __launch_bounds__(256) mlp2_kernel(
    const float* __restrict__ h1,
    const float* __restrict__ m2w, const float* __restrict__ m2b,
    const float* __restrict__ clw, const float* __restrict__ clb,
    float* __restrict__ ffout, float* __restrict__ flowout)
{
    __shared__ __align__(16) float sm2[128][64];   // transposed: sm2[c][j]
    __shared__ __align__(16) float xs[8][128];
    __shared__ __align__(16) float sb[64];
    __shared__ __align__(16) float scl[3][64];
    __shared__ float sclb[3];
    __shared__ float ffs[32][65];
    __shared__ float flows[32][3];

    const int t = threadIdx.x;
    for (int i = t; i < 64 * 128; i += 256) {
        int j = i >> 7, c = i & 127;
        sm2[c][j] = m2w[i];
    }
    if (t < 64)  sb[t] = m2b[t];
    if (t < 192) scl[t / 64][t % 64] = clw[t];
    if (t < 3)   sclb[t] = clb[t];
    __syncthreads();

    const int w = t >> 5, lane = t & 31;
    const int p0 = blockIdx.x * 32;

    #pragma unroll
    for (int it = 0; it < 4; it++) {
        int pl = (it << 3) + w;
        int p  = p0 + pl;
        const float* xr = h1 + (size_t)p * 128;
        ((float4*)xs[w])[lane] = ((const float4*)xr)[lane];
        __syncwarp();

        float a0 = sb[2*lane], a1 = sb[2*lane + 1];
        #pragma unroll 4
        for (int c = 0; c < 128; c++) {
            float xc = xs[w][c];
            float2 mv = ((const float2*)sm2[c])[lane];
            a0 += mv.x * xc;
            a1 += mv.y * xc;
        }
        a0 = lrelu(a0);
        a1 = lrelu(a1);
        ffs[pl][2*lane]     = a0;
        ffs[pl][2*lane + 1] = a1;

        float pr0 = scl[0][2*lane]*a0 + scl[0][2*lane+1]*a1;
        float pr1 = scl[1][2*lane]*a0 + scl[1][2*lane+1]*a1;
        float pr2 = scl[2][2*lane]*a0 + scl[2][2*lane+1]*a1;
        #pragma unroll
        for (int off = 16; off > 0; off >>= 1) {
            pr0 += __shfl_down_sync(0xffffffffu, pr0, off);
            pr1 += __shfl_down_sync(0xffffffffu, pr1, off);
            pr2 += __shfl_down_sync(0xffffffffu, pr2, off);
        }
        if (lane == 0) {
            flows[pl][0] = pr0 + sclb[0];
            flows[pl][1] = pr1 + sclb[1];
            flows[pl][2] = pr2 + sclb[2];
        }
        __syncwarp();
    }
    __syncthreads();

    const int b  = p0 >> 13;
    const int n0 = p0 & (Nn - 1);
    for (int i = t; i < 64 * 32; i += 256) {
        int j = i >> 5, nl = i & 31;
        ffout[((size_t)b * 64 + j) * Nn + n0 + nl] = ffs[nl][j];
    }
    if (t < 96) {
        int ii = t / 32, nl = t % 32;
        flowout[((size_t)b * 3 + ii) * Nn + n0 + nl] = flows[nl][ii];
    }
}

// ============================================================================
extern "C" void kernel_launch(void* const* d_in, const int* in_sizes, int n_in,
                              void* d_out, int out_size) {
    const float* xyz    = (const float*)d_in[0];
    const float* feat   = (const float*)d_in[1];
    const int*   knn    = (const int*)  d_in[2];
    const float* wn1_w  = (const float*)d_in[3];
    const float* wn1_b  = (const float*)d_in[4];
    const float* lin1_w = (const float*)d_in[5];
    const float* lin1_b = (const float*)d_in[6];
    const float* wn2_w  = (const float*)d_in[7];
    const float* wn2_b  = (const float*)d_in[8];
    const float* lin2_w = (const float*)d_in[9];
    const float* lin2_b = (const float*)d_in[10];
    const float* m1_w   = (const float*)d_in[11];
    const float* m1_b   = (const float*)d_in[12];
    const float* m2_w   = (const float*)d_in[13];
    const float* m2_b   = (const float*)d_in[14];
    const float* cl_w   = (const float*)d_in[15];
    const float* cl_b   = (const float*)d_in[16];

    float* out = (float*)d_out;
    float* ffout   = out;                       // flow_feat [B,64,N]
    float* flowout = out + (size_t)NPTS * 64;   // flow      [B,3,N]

    static float *fc1 = nullptr, *fc2 = nullptr, *agg = nullptr,
                 *f2 = nullptr, *h1 = nullptr,
                 *w1 = nullptr, *w2 = nullptr, *wm = nullptr;
    if (!fc1) {
        cudaGetSymbolAddress((void**)&fc1, g_fc1);
        cudaGetSymbolAddress((void**)&fc2, g_fc2);
        cudaGetSymbolAddress((void**)&agg, g_agg);
        cudaGetSymbolAddress((void**)&f2,  g_f2);
        cudaGetSymbolAddress((void**)&h1,  g_h1);
        cudaGetSymbolAddress((void**)&w1,  g_w1);
        cudaGetSymbolAddress((void**)&w2,  g_w2);
        cudaGetSymbolAddress((void**)&wm,  g_wm);
    }

    // weight prep: tf32-convert + zero-pad to row stride AGGP / 128
    {
        int tw = 128 * AGGP;
        wcvt_kernel<<<(tw + 255) / 256, 256>>>(lin1_w, w1, AGGK, AGGP, tw);
        wcvt_kernel<<<(tw + 255) / 256, 256>>>(lin2_w, w2, AGGK, AGGP, tw);
        int tm = 128 * 128;
        wcvt_kernel<<<(tm + 255) / 256, 256>>>(m1_w, wm, 128, 128, tm);
    }
    // pack input features + xyz into point-major rows
    {
        int total = NPTS * FCLD;
        pack_kernel<<<(total + 255) / 256, 256>>>(xyz, feat, fc1, fc2);
    }
    // point conv 1
    stage_a_kernel<<<NPTS / 8, 256>>>(fc1, knn, wn1_w, wn1_b, agg);
    gemm_tf32_async<<<NPTS / 128, 256>>>(agg, w1, lin1_b, fc2, AGGP, FCLD, 1, 0);
    // point conv 2 (output f2 as tf32 bits — m1 consumes it raw)
    stage_a_kernel<<<NPTS / 8, 256>>>(fc2, knn, wn2_w, wn2_b, agg);
    gemm_tf32_async<<<NPTS / 128, 256>>>(agg, w2, lin2_b, f2, AGGP, 128, 1, 1);
    // MLP layer 1 (K=128)
    gemm_tf32_async<<<NPTS / 128, 256>>>(f2, wm, m1_b, h1, 128, 128, 1, 0);
    // MLP layer 2 + conv_last fused, channel-major outputs
    mlp2_kernel<<<NPTS / 32, 256>>>(h1, m2_w, m2_b, cl_w, cl_b, ffout, flowout);
}

// round 11
// speedup vs baseline: 1.6741x; 1.0819x over previous
#include <cuda_runtime.h>
#include <cstdint>

#define NEG 0.1f
#define Bb 4
#define Nn 8192
#define Kk 16
#define CIN 131      // 3 + 128 (logical feat_cat channels)
#define FCLD 132     // row stride: [feat 0..127][xyz 128..130][pad 131]
#define AGGK 1048    // 8 * 131 (real K of the big GEMMs)
#define AGGP 1056    // padded row stride (66 * 16); pad cols statically zero
#define NPTS (Bb*Nn) // 32768

#define GSTAGES 3
#define GEMM_SMEM (GSTAGES * 2 * 128 * 20 * 4)   // 61440 B dynamic

// ---- scratch (static device globals; no runtime allocation) ----
__device__ __align__(16) float g_fc1[NPTS * FCLD];   // 16.5 MB
__device__ __align__(16) float g_fc2[NPTS * FCLD];   // 16.5 MB
__device__ __align__(16) float g_agg[(size_t)NPTS * AGGP]; // 138 MB, tf32 bits; pads stay 0
__device__ __align__(16) float g_f2 [NPTS * 128];    // 16.8 MB (tf32 bits)
__device__ __align__(16) float g_h1 [NPTS * 128];    // 16.8 MB
__device__ __align__(16) float g_w1 [128 * AGGP];    // lin1_w tf32, padded
__device__ __align__(16) float g_w2 [128 * AGGP];    // lin2_w tf32, padded
__device__ __align__(16) float g_wm [128 * 128];     // m1_w tf32

__device__ __forceinline__ float lrelu(float v) { return v > 0.f ? v : NEG * v; }

__device__ __forceinline__ uint32_t f2tf32(float f) {
    uint32_t u;
    asm("cvt.rna.tf32.f32 %0, %1;" : "=r"(u) : "f"(f));
    return u;
}

__device__ __forceinline__ void mma_tf32(float4& c,
                                         const uint32_t* a, const uint32_t* b) {
    asm volatile(
        "mma.sync.aligned.m16n8k8.row.col.f32.tf32.tf32.f32 "
        "{%0,%1,%2,%3}, {%4,%5,%6,%7}, {%8,%9}, {%0,%1,%2,%3};"
        : "+f"(c.x), "+f"(c.y), "+f"(c.z), "+f"(c.w)
        : "r"(a[0]), "r"(a[1]), "r"(a[2]), "r"(a[3]), "r"(b[0]), "r"(b[1]));
}

__device__ __forceinline__ void cpa16(uint32_t* smem_ptr, const void* g) {
    uint32_t s = (uint32_t)__cvta_generic_to_shared(smem_ptr);
    asm volatile("cp.async.cg.shared.global [%0], [%1], 16;" :: "r"(s), "l"(g));
}
__device__ __forceinline__ void cpa_commit() {
    asm volatile("cp.async.commit_group;");
}

// ============================================================================
// Weight prep: dst[r][c<ksrc ? tf32(src) : 0], row stride kdst.
// ============================================================================
__global__ void wcvt_kernel(const float* __restrict__ src, float* __restrict__ dst,
                            int ksrc, int kdst, int total) {
    int i = blockIdx.x * blockDim.x + threadIdx.x;
    if (i >= total) return;
    int r = i / kdst, c = i - r * kdst;
    float v = (c < ksrc) ? src[r * ksrc + c] : 0.f;
    dst[i] = __uint_as_float(f2tf32(v));
}

// ============================================================================
// Pack (feat part): 32x32 smem-tile transpose, coalesced on both sides.
// fc1[p][c] = feat[b][c][n],  p = b*Nn + n.
// ============================================================================
__global__ void __launch_bounds__(256) packT_kernel(
    const float* __restrict__ feat, float* __restrict__ fc1)
{
    __shared__ float tile[32][33];
    const int t  = threadIdx.x;
    const int tx = t & 31, ty = t >> 5;      // ty 0..7
    const int p0 = blockIdx.x << 5;          // 32 points
    const int c0 = blockIdx.y << 5;          // 32 channels
    const int b  = p0 >> 13;
    const int n0 = p0 & (Nn - 1);

    #pragma unroll
    for (int i = 0; i < 4; i++) {
        int c = c0 + ty + (i << 3);
        tile[ty + (i << 3)][tx] = feat[((size_t)b * 128 + c) * Nn + n0 + tx];
    }
    __syncthreads();
    #pragma unroll
    for (int i = 0; i < 4; i++) {
        int pr = ty + (i << 3);
        fc1[(size_t)(p0 + pr) * FCLD + c0 + tx] = tile[tx][pr];
    }
}

// ============================================================================
// Pack (xyz + pad): fc1/fc2 cols 128..131 <- xyz / 0.
// ============================================================================
__global__ void packXYZ_kernel(const float* __restrict__ xyz,
                               float* __restrict__ fc1, float* __restrict__ fc2)
{
    int tid = blockIdx.x * blockDim.x + threadIdx.x;
    if (tid >= NPTS * 4) return;
    int p = tid >> 2, c = tid & 3;
    int b = p >> 13, n = p & (Nn - 1);
    float v = (c < 3) ? xyz[((size_t)b * 3 + c) * Nn + n] : 0.f;
    fc1[(size_t)p * FCLD + 128 + c] = v;
    fc2[(size_t)p * FCLD + 128 + c] = v;
}

// ============================================================================
// Stage A (hoisted-weight): per point gather K=16 neighbors,
// w = lrelu(wn_w@rel + wn_b), agg[o][c] = sum_k w[o,k]*featcat[c,k].
// Output stored as tf32 bits (same cvt.rna the GEMM fill used to apply).
// ============================================================================
__global__ void __launch_bounds__(256) stage_a_kernel(
    const float* __restrict__ fc, const int* __restrict__ idx,
    const float* __restrict__ wn_w, const float* __restrict__ wn_b,
    float* __restrict__ agg)
{
    __shared__ float sww[24];
    __shared__ float swb[8];
    const int t = threadIdx.x;
    if (t < 24) sww[t] = wn_w[t];
    if (t < 8)  swb[t] = wn_b[t];
    __syncthreads();

    const int warp = t >> 5, lane = t & 31;
    const int p = blockIdx.x * 8 + warp;
    const int b = p >> 13;

    const float* crow = fc + (size_t)p * FCLD;
    const float cx = crow[128], cy = crow[129], cz = crow[130];
    const int* ip = idx + (size_t)p * Kk;

    const int lane16 = lane & 15;
    const int m_mine = ip[lane16];
    const float* rowm = fc + (size_t)(b * Nn + m_mine) * FCLD;
    const float rxm = rowm[128] - cx, rym = rowm[129] - cy, rzm = rowm[130] - cz;
    float wv[8];
    #pragma unroll
    for (int o = 0; o < 8; o++)
        wv[o] = lrelu(sww[o*3]*rxm + sww[o*3+1]*rym + sww[o*3+2]*rzm + swb[o]);

    float acc0[8], acc1[8], acc2[8], acc3[8], acc4[8];
    #pragma unroll
    for (int o = 0; o < 8; o++) { acc0[o]=0.f; acc1[o]=0.f; acc2[o]=0.f; acc3[o]=0.f; acc4[o]=0.f; }

    const int phys0 = (lane < 3) ? (128 + lane) : (lane - 3);

    #pragma unroll 4
    for (int k = 0; k < Kk; k++) {
        const int m = __shfl_sync(0xffffffffu, m_mine, k);
        const float* row = fc + ((size_t)(b * Nn + m)) * FCLD;
        float w[8];
        #pragma unroll
        for (int o = 0; o < 8; o++) w[o] = __shfl_sync(0xffffffffu, wv[o], k);
        float f0 = row[phys0];
        float f1 = row[lane + 29];
        float f2 = row[lane + 61];
        float f3 = row[lane + 93];
        float f4 = (lane < 3) ? row[lane + 125] : 0.f;
        #pragma unroll
        for (int o = 0; o < 8; o++) {
            acc0[o] += w[o] * f0;
            acc1[o] += w[o] * f1;
            acc2[o] += w[o] * f2;
            acc3[o] += w[o] * f3;
            acc4[o] += w[o] * f4;
        }
    }

    float* out = agg + (size_t)p * AGGP;
    #pragma unroll
    for (int o = 0; o < 8; o++) {
        out[o*CIN + lane]       = __uint_as_float(f2tf32(acc0[o]));
        out[o*CIN + lane + 32]  = __uint_as_float(f2tf32(acc1[o]));
        out[o*CIN + lane + 64]  = __uint_as_float(f2tf32(acc2[o]));
        out[o*CIN + lane + 96]  = __uint_as_float(f2tf32(acc3[o]));
        if (lane < 3) out[o*CIN + lane + 128] = __uint_as_float(f2tf32(acc4[o]));
    }
}

// ============================================================================
// tf32 GEMM, 3-stage cp.async ring (dynamic smem). A and W hold tf32 bits,
// row stride Kpad (pads zero). out[m][j] = act(sum_k A[m][k]*W[j][k]+b[j]).
// BM=BN=128, BK=16, 256 threads, warp tile 32x64.
// One __syncthreads per K-tile: the buffer refilled at step kt was consumed
// at kt-1, which all warps finished (they passed this iteration's barrier).
// ============================================================================
__global__ void __launch_bounds__(256) gemm_tf32_async(
    const float* __restrict__ A, const float* __restrict__ W,
    const float* __restrict__ bias, float* __restrict__ out,
    int Kpad, int ldout, int do_relu, int out_tf32)
{
    extern __shared__ __align__(16) uint32_t dynsmem[];
    typedef uint32_t Tile[128][20];
    Tile* As = (Tile*)dynsmem;                          // GSTAGES tiles
    Tile* Ws = (Tile*)(dynsmem + GSTAGES * 128 * 20);   // GSTAGES tiles

    const int t    = threadIdx.x;
    const int m0   = blockIdx.x << 7;
    const int lr   = t >> 1;            // 0..127 load row
    const int lcw  = (t & 1) << 3;      // word col 0 or 8

    const int wid  = t >> 5, lane = t & 31;
    const int wm   = (wid & 3) << 5;
    const int wn   = (wid >> 2) << 6;
    const int g    = lane >> 2;
    const int tg   = lane & 3;

    float4 c[2][8];
    #pragma unroll
    for (int im = 0; im < 2; im++)
        #pragma unroll
        for (int jn = 0; jn < 8; jn++) c[im][jn] = make_float4(0.f,0.f,0.f,0.f);

    const int niter = Kpad >> 4;
    const float* Ap = A + (size_t)(m0 + lr) * Kpad + lcw;
    const float* Wp = W + (size_t)lr * Kpad + lcw;

    // ---- prologue: issue tiles 0 and 1 into stages 0 and 1 ----
    cpa16(&As[0][lr][lcw],     Ap);
    cpa16(&As[0][lr][lcw + 4], Ap + 4);
    cpa16(&Ws[0][lr][lcw],     Wp);
    cpa16(&Ws[0][lr][lcw + 4], Wp + 4);
    cpa_commit();
    if (niter > 1) {
        cpa16(&As[1][lr][lcw],     Ap + 16);
        cpa16(&As[1][lr][lcw + 4], Ap + 20);
        cpa16(&Ws[1][lr][lcw],     Wp + 16);
        cpa16(&Ws[1][lr][lcw + 4], Wp + 20);
        cpa_commit();
    }

    int s = 0;   // stage being computed
    for (int kt = 0; kt < niter; kt++) {
        if (kt + 1 < niter) asm volatile("cp.async.wait_group 1;");
        else                asm volatile("cp.async.wait_group 0;");
        __syncthreads();

        #pragma unroll
        for (int kk = 0; kk < 16; kk += 8) {
            uint32_t a[2][4];
            #pragma unroll
            for (int im = 0; im < 2; im++) {
                int row = wm + (im << 4);
                a[im][0] = As[s][row + g    ][kk + tg    ];
                a[im][1] = As[s][row + g + 8][kk + tg    ];
                a[im][2] = As[s][row + g    ][kk + tg + 4];
                a[im][3] = As[s][row + g + 8][kk + tg + 4];
            }
            uint32_t bfr[8][2];
            #pragma unroll
            for (int jn = 0; jn < 8; jn++) {
                int col = wn + (jn << 3);
                bfr[jn][0] = Ws[s][col + g][kk + tg    ];
                bfr[jn][1] = Ws[s][col + g][kk + tg + 4];
            }
            #pragma unroll
            for (int im = 0; im < 2; im++)
                #pragma unroll
                for (int jn = 0; jn < 8; jn++)
                    mma_tf32(c[im][jn], a[im], bfr[jn]);
        }

        if (kt + 2 < niter) {
            const int kb = (kt + 2) << 4;
            int pf = s + 2; if (pf >= GSTAGES) pf -= GSTAGES;
            cpa16(&As[pf][lr][lcw],     Ap + kb);
            cpa16(&As[pf][lr][lcw + 4], Ap + kb + 4);
            cpa16(&Ws[pf][lr][lcw],     Wp + kb);
            cpa16(&Ws[pf][lr][lcw + 4], Wp + kb + 4);
            cpa_commit();
        }
        s++; if (s >= GSTAGES) s = 0;
    }

    // ---- epilogue: bias + lrelu (+ optional tf32 cvt), float2 stores ----
    #pragma unroll
    for (int jn = 0; jn < 8; jn++) {
        int col = wn + (jn << 3) + (tg << 1);
        float b0 = bias[col], b1 = bias[col + 1];
        #pragma unroll
        for (int im = 0; im < 2; im++) {
            int row = m0 + wm + (im << 4) + g;
            float v0 = c[im][jn].x + b0;
            float v1 = c[im][jn].y + b1;
            float v2 = c[im][jn].z + b0;
            float v3 = c[im][jn].w + b1;
            if (do_relu) { v0 = lrelu(v0); v1 = lrelu(v1); v2 = lrelu(v2); v3 = lrelu(v3); }
            if (out_tf32) {
                v0 = __uint_as_float(f2tf32(v0));
                v1 = __uint_as_float(f2tf32(v1));
                v2 = __uint_as_float(f2tf32(v2));
                v3 = __uint_as_float(f2tf32(v3));
            }
            *(float2*)(out + (size_t)row * ldout + col)       = make_float2(v0, v1);
            *(float2*)(out + (size_t)(row + 8) * ldout + col) = make_float2(v2, v3);
        }
    }
}

// ============================================================================
// Fused tail: ff = lrelu(m2_w @ h1 + m2_b)  (64 ch), flow = cl_w @ ff + cl_b.
// ============================================================================
__global__ void __launch_bounds__(256) mlp2_kernel(
    const float* __restrict__ h1,
    const float* __restrict__ m2w, const float* __restrict__ m2b,
    const float* __restrict__ clw, const float* __restrict__ clb,
    float* __restrict__ ffout, float* __restrict__ flowout)
{
    __shared__ __align__(16) float sm2[128][64];   // transposed: sm2[c][j]
    __shared__ __align__(16) float xs[8][128];
    __shared__ __align__(16) float sb[64];
    __shared__ __align__(16) float scl[3][64];
    __shared__ float sclb[3];
    __shared__ float ffs[32][65];
    __shared__ float flows[32][3];

    const int t = threadIdx.x;
    for (int i = t; i < 64 * 128; i += 256) {
        int j = i >> 7, c = i & 127;
        sm2[c][j] = m2w[i];
    }
    if (t < 64)  sb[t] = m2b[t];
    if (t < 192) scl[t / 64][t % 64] = clw[t];
    if (t < 3)   sclb[t] = clb[t];
    __syncthreads();

    const int w = t >> 5, lane = t & 31;
    const int p0 = blockIdx.x * 32;

    #pragma unroll
    for (int it = 0; it < 4; it++) {
        int pl = (it << 3) + w;
        int p  = p0 + pl;
        const float* xr = h1 + (size_t)p * 128;
        ((float4*)xs[w])[lane] = ((const float4*)xr)[lane];
        __syncwarp();

        float a0 = sb[2*lane], a1 = sb[2*lane + 1];
        #pragma unroll 4
        for (int c = 0; c < 128; c++) {
            float xc = xs[w][c];
            float2 mv = ((const float2*)sm2[c])[lane];
            a0 += mv.x * xc;
            a1 += mv.y * xc;
        }
        a0 = lrelu(a0);
        a1 = lrelu(a1);
        ffs[pl][2*lane]     = a0;
        ffs[pl][2*lane + 1] = a1;

        float pr0 = scl[0][2*lane]*a0 + scl[0][2*lane+1]*a1;
        float pr1 = scl[1][2*lane]*a0 + scl[1][2*lane+1]*a1;
        float pr2 = scl[2][2*lane]*a0 + scl[2][2*lane+1]*a1;
        #pragma unroll
        for (int off = 16; off > 0; off >>= 1) {
            pr0 += __shfl_down_sync(0xffffffffu, pr0, off);
            pr1 += __shfl_down_sync(0xffffffffu, pr1, off);
            pr2 += __shfl_down_sync(0xffffffffu, pr2, off);
        }
        if (lane == 0) {
            flows[pl][0] = pr0 + sclb[0];
            flows[pl][1] = pr1 + sclb[1];
            flows[pl][2] = pr2 + sclb[2];
        }
        __syncwarp();
    }
    __syncthreads();

    const int b  = p0 >> 13;
    const int n0 = p0 & (Nn - 1);
    for (int i = t; i < 64 * 32; i += 256) {
        int j = i >> 5, nl = i & 31;
        ffout[((size_t)b * 64 + j) * Nn + n0 + nl] = ffs[nl][j];
    }
    if (t < 96) {
        int ii = t / 32, nl = t % 32;
        flowout[((size_t)b * 3 + ii) * Nn + n0 + nl] = flows[nl][ii];
    }
}

// ============================================================================
extern "C" void kernel_launch(void* const* d_in, const int* in_sizes, int n_in,
                              void* d_out, int out_size) {
    const float* xyz    = (const float*)d_in[0];
    const float* feat   = (const float*)d_in[1];
    const int*   knn    = (const int*)  d_in[2];
    const float* wn1_w  = (const float*)d_in[3];
    const float* wn1_b  = (const float*)d_in[4];
    const float* lin1_w = (const float*)d_in[5];
    const float* lin1_b = (const float*)d_in[6];
    const float* wn2_w  = (const float*)d_in[7];
    const float* wn2_b  = (const float*)d_in[8];
    const float* lin2_w = (const float*)d_in[9];
    const float* lin2_b = (const float*)d_in[10];
    const float* m1_w   = (const float*)d_in[11];
    const float* m1_b   = (const float*)d_in[12];
    const float* m2_w   = (const float*)d_in[13];
    const float* m2_b   = (const float*)d_in[14];
    const float* cl_w   = (const float*)d_in[15];
    const float* cl_b   = (const float*)d_in[16];

    float* out = (float*)d_out;
    float* ffout   = out;                       // flow_feat [B,64,N]
    float* flowout = out + (size_t)NPTS * 64;   // flow      [B,3,N]

    static float *fc1 = nullptr, *fc2 = nullptr, *agg = nullptr,
                 *f2 = nullptr, *h1 = nullptr,
                 *w1 = nullptr, *w2 = nullptr, *wm = nullptr;
    if (!fc1) {
        cudaGetSymbolAddress((void**)&fc1, g_fc1);
        cudaGetSymbolAddress((void**)&fc2, g_fc2);
        cudaGetSymbolAddress((void**)&agg, g_agg);
        cudaGetSymbolAddress((void**)&f2,  g_f2);
        cudaGetSymbolAddress((void**)&h1,  g_h1);
        cudaGetSymbolAddress((void**)&w1,  g_w1);
        cudaGetSymbolAddress((void**)&w2,  g_w2);
        cudaGetSymbolAddress((void**)&wm,  g_wm);
        cudaFuncSetAttribute(gemm_tf32_async,
                             cudaFuncAttributeMaxDynamicSharedMemorySize,
                             GEMM_SMEM);
    }

    // weight prep: tf32-convert + zero-pad to row stride AGGP / 128
    {
        int tw = 128 * AGGP;
        wcvt_kernel<<<(tw + 255) / 256, 256>>>(lin1_w, w1, AGGK, AGGP, tw);
        wcvt_kernel<<<(tw + 255) / 256, 256>>>(lin2_w, w2, AGGK, AGGP, tw);
        int tm = 128 * 128;
        wcvt_kernel<<<(tm + 255) / 256, 256>>>(m1_w, wm, 128, 128, tm);
    }
    // pack: coalesced transpose for feat, small kernel for xyz+pad
    {
        dim3 gT(NPTS / 32, 4);
        packT_kernel<<<gT, 256>>>(feat, fc1);
        packXYZ_kernel<<<(NPTS * 4 + 255) / 256, 256>>>(xyz, fc1, fc2);
    }
    // point conv 1
    stage_a_kernel<<<NPTS / 8, 256>>>(fc1, knn, wn1_w, wn1_b, agg);
    gemm_tf32_async<<<NPTS / 128, 256, GEMM_SMEM>>>(agg, w1, lin1_b, fc2, AGGP, FCLD, 1, 0);
    // point conv 2 (output f2 as tf32 bits — m1 consumes it raw)
    stage_a_kernel<<<NPTS / 8, 256>>>(fc2, knn, wn2_w, wn2_b, agg);
    gemm_tf32_async<<<NPTS / 128, 256, GEMM_SMEM>>>(agg, w2, lin2_b, f2, AGGP, 128, 1, 1);
    // MLP layer 1 (K=128)
    gemm_tf32_async<<<NPTS / 128, 256, GEMM_SMEM>>>(f2, wm, m1_b, h1, 128, 128, 1, 0);
    // MLP layer 2 + conv_last fused, channel-major outputs
    mlp2_kernel<<<NPTS / 32, 256>>>(h1, m2_w, m2_b, cl_w, cl_b, ffout, flowout);
}